// round 17
// baseline (speedup 1.0000x reference)
#include <cuda_runtime.h>
#include <cstdint>

#define EPSF 1e-20f

constexpr int B = 8, C = 32, O = 32, H = 256, W = 256;
constexpr int HW = H * W;                         // 65536
constexpr long long NTOT = (long long)B * O * HW;

// Scratch (allocation-free rule: __device__ globals). 128 MiB total.
__device__ float g_p[B * C * HW];                 // conv nominator (raw)
__device__ float g_q[B * C * HW];                 // conv denominator (raw)

// k0 outputs
__device__ unsigned long long g_cwT2[C * O];      // softplus(channel_weight) transposed [c][o], pair-packed
__device__ float g_scaleCG;                       // 1/(sum_sw * sum_cw)

__device__ __forceinline__ float softplusf(float x) { return __logf(1.0f + __expf(x)); }

__device__ __forceinline__ unsigned long long pack2(float lo, float hi) {
    unsigned long long v;
    asm("mov.b64 %0, {%1, %2};" : "=l"(v) : "f"(lo), "f"(hi));
    return v;
}
__device__ __forceinline__ void unpack2(unsigned long long v, float& lo, float& hi) {
    asm("mov.b64 {%0, %1}, %2;" : "=f"(lo), "=f"(hi) : "l"(v));
}
__device__ __forceinline__ void fma2(unsigned long long& acc, unsigned long long a, unsigned long long w) {
    asm("fma.rn.f32x2 %0, %1, %2, %0;" : "+l"(acc) : "l"(a), "l"(w));
}
__device__ __forceinline__ void cp_async16(unsigned int smem_addr, const void* gptr) {
    asm volatile("cp.async.cg.shared.global [%0], [%1], 16;" :: "r"(smem_addr), "l"(gptr));
}

// ---------------------------------------------------------------------------
// K0: packed transposed channel weights + 1/(sum_sw*sum_cw).
// ---------------------------------------------------------------------------
__global__ void k0_weights(const float* __restrict__ sw_raw,
                           const float* __restrict__ cw_raw) {
    __shared__ float red[64];
    const int t = threadIdx.x;            // 1024 threads

    float s1 = 0.f;
    for (int i = t; i < C * 25; i += 1024) s1 += softplusf(sw_raw[i]);

    float s2 = 0.f;
    for (int i = t; i < O * C; i += 1024) {
        int c = i >> 5, o = i & 31;       // i = c*32 + o
        float w = softplusf(cw_raw[o * C + c]);
        g_cwT2[i] = pack2(w, w);
        s2 += w;
    }
#pragma unroll
    for (int o = 16; o; o >>= 1) {
        s1 += __shfl_down_sync(~0u, s1, o);
        s2 += __shfl_down_sync(~0u, s2, o);
    }
    if ((t & 31) == 0) { red[t >> 5] = s1; red[32 + (t >> 5)] = s2; }
    __syncthreads();
    if (t == 0) {
        float a = 0.f, b = 0.f;
        for (int i = 0; i < 32; i++) { a += red[i]; b += red[32 + i]; }
        g_scaleCG = 1.0f / (a * b);
    }
}

// ---------------------------------------------------------------------------
// K12: simplified prop (p = alpha*cgx*gx, q = alpha*cgx + beta*cd^2*interior)
// + depthwise 5x5 conv (raw weights; 1/sum_sw cancels in K3's ratio and is
// folded into g_scaleCG). One block = one (b, c, 64x32 tile).
// Outputs de-interleaved into g_p / g_q planes.
// ---------------------------------------------------------------------------
constexpr int TW = 64, TH = 32;           // tile width/height
constexpr int HST = 70;                   // halo row stride in u64 (even -> 16B aligned)

__global__ __launch_bounds__(256) void k12_prop_dwconv(
    const float* __restrict__ cd, const float* __restrict__ gx,
    const float* __restrict__ cgx, const float* __restrict__ wprop,
    const float* __restrict__ sw_raw) {

    __shared__ unsigned long long sPQ[36 * HST];   // 36 x 68 halo (+pad)
    __shared__ unsigned long long sw2[25];

    const int tid = threadIdx.x;
    const int b = blockIdx.z, c = blockIdx.y;
    const int h0 = (blockIdx.x >> 2) * TH;         // 8 row-tiles
    const int w0 = (blockIdx.x & 3) * TW;          // 4 col-tiles

    if (tid < 25) {
        float w = softplusf(sw_raw[c * 25 + tid]);
        sw2[tid] = pack2(w, w);
    }
    const float wp = softplusf(wprop[c]);
    const float beta = __fdividef(1.0f, 1.0f + wp);
    const float alpha = wp * beta;

    const size_t plane = ((size_t)b * C + c) * HW;

    // Phase A: 36 rows x 34 aligned pixel-pairs = 1224 jobs
    for (int idx = tid; idx < 36 * 34; idx += 256) {
        int hh = idx / 34, pw = idx - hh * 34;
        int gh = h0 + hh - 2, gw = w0 + pw * 2 - 2;   // gw even; pair fully in or out
        unsigned long long v0 = 0ULL, v1 = 0ULL;
        if ((unsigned)gh < (unsigned)H && (unsigned)gw < (unsigned)W) {
            size_t g = plane + (size_t)gh * W + gw;
            float2 cd2 = *(const float2*)(cd + g);
            float2 gx2 = *(const float2*)(gx + g);
            float2 cg2 = *(const float2*)(cgx + g);
            float m0 = alpha * cg2.x, m1 = alpha * cg2.y;
            float cz0 = (gw == 0)         ? 0.f : cd2.x;   // left edge col
            float cz1 = (gw + 1 == W - 1) ? 0.f : cd2.y;   // right edge col
            v0 = pack2(m0 * gx2.x, fmaf(beta * cz0, cz0, m0));
            v1 = pack2(m1 * gx2.y, fmaf(beta * cz1, cz1, m1));
        }
        *(ulonglong2*)(sPQ + hh * HST + pw * 2) = make_ulonglong2(v0, v1);
    }
    __syncthreads();

    // Phase B: thread (tx, ty) -> cols 2tx..2tx+1, rows ty*4..ty*4+3
    const int tx = tid & 31, ty = tid >> 5;
    const int r0 = ty * 4;
    const int c0 = 2 * tx;
    unsigned long long acc0[4] = {0ULL, 0ULL, 0ULL, 0ULL};  // left col
    unsigned long long acc1[4] = {0ULL, 0ULL, 0ULL, 0ULL};  // right col

#pragma unroll
    for (int i = 0; i < 8; i++) {                  // halo rows r0 .. r0+7
        unsigned long long x[6];
        const unsigned long long* rp = sPQ + (r0 + i) * HST + c0;
        *(ulonglong2*)(x + 0) = *(const ulonglong2*)(rp + 0);
        *(ulonglong2*)(x + 2) = *(const ulonglong2*)(rp + 2);
        *(ulonglong2*)(x + 4) = *(const ulonglong2*)(rp + 4);
#pragma unroll
        for (int k = 0; k < 4; k++) {
            const int wr = i - k;
            if (wr >= 0 && wr < 5) {
#pragma unroll
                for (int j = 0; j < 5; j++) {
                    unsigned long long w = sw2[wr * 5 + j];
                    fma2(acc0[k], x[j], w);
                    fma2(acc1[k], x[j + 1], w);
                }
            }
        }
    }

    // de-interleaved stores: (n left, n right) -> g_p, (d left, d right) -> g_q
#pragma unroll
    for (int k = 0; k < 4; k++) {
        float nL, dL, nR, dR;
        unpack2(acc0[k], nL, dL);
        unpack2(acc1[k], nR, dR);
        size_t g = plane + (size_t)(h0 + r0 + k) * W + (w0 + c0);
        *(float2*)(g_p + g) = make_float2(nL, nR);
        *(float2*)(g_q + g) = make_float2(dL, dR);
    }
}

// ---------------------------------------------------------------------------
// K3: 1x1 channel conv (32 -> 32). Block = 128 contiguous pixels of one batch.
// p/q staged via cp.async into [c][px] smem; channel weights in SMEM
// (not registers) -> fewer regs, 3 blocks/SM (occ 37.5%).
// Compute: warp = 16 px (4 groups of 4), lane = output channel.
// ---------------------------------------------------------------------------
constexpr int K3_PIX = 128;
constexpr int K3_THREADS = 256;
constexpr int ROW = 132;                          // float row stride (16B-aligned)
constexpr int STG_STRIDE = 129;                   // floats; conflict-free lane writes

__global__ __launch_bounds__(K3_THREADS) void k3_chconv(const float* __restrict__ bias,
                                                        float* __restrict__ out) {
    __shared__ float sP[C * ROW];                 // 16896 B
    __shared__ float sQ[C * ROW];                 // 16896 B
    __shared__ unsigned long long cw2s[C * O];    // 8192 B
    __shared__ float stage[2 * O * STG_STRIDE];   // 33024 B

    const int tid = threadIdx.x;
    const int lane = tid & 31;
    const int warp = tid >> 5;
    const int b = blockIdx.y;
    const int pix0 = blockIdx.x * K3_PIX;

    // async copy: 32 channels x 128 px per plane, 16B granularity
    const size_t base = (size_t)b * C * HW + pix0;
#pragma unroll
    for (int it = 0; it < 4; it++) {              // 1024 float4 per plane / 256 thr
        int idx = it * K3_THREADS + tid;
        int c = idx >> 5;                         // 32 float4 per row
        int x4 = (idx & 31) * 4;
        cp_async16((unsigned int)__cvta_generic_to_shared(sP + c * ROW + x4),
                   g_p + base + (size_t)c * HW + x4);
        cp_async16((unsigned int)__cvta_generic_to_shared(sQ + c * ROW + x4),
                   g_q + base + (size_t)c * HW + x4);
    }
    asm volatile("cp.async.commit_group;" ::: "memory");

    // weights into smem while the async copies fly
    for (int i = tid; i < C * O; i += K3_THREADS) cw2s[i] = g_cwT2[i];
    const float bs = bias[lane];
    const float sccg = g_scaleCG;

    asm volatile("cp.async.wait_group 0;" ::: "memory");
    __syncthreads();

#pragma unroll
    for (int gi = 0; gi < 4; gi++) {              // 4 groups of 4 px per warp
        const int px = warp * 16 + gi * 4;
        const float* pP = sP + px;
        const float* pQ = sQ + px;
        unsigned long long an01 = 0ULL, an23 = 0ULL, ad01 = 0ULL, ad23 = 0ULL;
#pragma unroll
        for (int cc = 0; cc < C; cc++) {
            float4 p4 = *(const float4*)(pP + cc * ROW);   // broadcast LDS.128
            float4 q4 = *(const float4*)(pQ + cc * ROW);
            unsigned long long w = cw2s[cc * O + lane];    // conflict-free LDS.64
            fma2(an01, pack2(p4.x, p4.y), w);
            fma2(an23, pack2(p4.z, p4.w), w);
            fma2(ad01, pack2(q4.x, q4.y), w);
            fma2(ad23, pack2(q4.z, q4.w), w);
        }
        float n[4], dn[4];
        unpack2(an01, n[0], n[1]);  unpack2(an23, n[2], n[3]);
        unpack2(ad01, dn[0], dn[1]); unpack2(ad23, dn[2], dn[3]);
#pragma unroll
        for (int j = 0; j < 4; j++) {
            stage[lane * STG_STRIDE + px + j]                  = __fdividef(n[j], dn[j] + EPSF) + bs;
            stage[O * STG_STRIDE + lane * STG_STRIDE + px + j] = dn[j] * sccg;
        }
    }
    __syncthreads();

    const size_t outb = (size_t)b * O * HW + pix0;
#pragma unroll
    for (int it = 0; it < (O * K3_PIX) / K3_THREADS; it++) {
        int idx = it * K3_THREADS + tid;
        int o = idx >> 7;
        int px = idx & (K3_PIX - 1);
        size_t g = outb + (size_t)o * HW + px;
        out[g]        = stage[o * STG_STRIDE + px];
        out[NTOT + g] = stage[O * STG_STRIDE + o * STG_STRIDE + px];
    }
}

// ---------------------------------------------------------------------------
extern "C" void kernel_launch(void* const* d_in, const int* in_sizes, int n_in,
                              void* d_out, int out_size) {
    const float* cd    = (const float*)d_in[1];
    const float* gx    = (const float*)d_in[2];
    const float* cgx   = (const float*)d_in[3];
    const float* wprop = (const float*)d_in[4];
    const float* sw    = (const float*)d_in[5];
    const float* cw    = (const float*)d_in[6];
    const float* bias  = (const float*)d_in[7];
    float* out = (float*)d_out;

    k0_weights<<<1, 1024>>>(sw, cw);

    dim3 g12(32, C, B);            // 4x8 tiles of 64x32, per (c, b)
    k12_prop_dwconv<<<g12, 256>>>(cd, gx, cgx, wprop, sw);

    dim3 g3(HW / K3_PIX, B);       // 512 pixel-chunks per batch
    k3_chconv<<<g3, K3_THREADS>>>(bias, out);
}